// round 12
// baseline (speedup 1.0000x reference)
#include <cuda_runtime.h>
#include <utility>
#include <math.h>

// ============================================================================
// Compile-time real-basis Wigner 3j (Clebsch-Gordan) coefficients.
// Evaluated by the C++ front end; every nonzero entry becomes an FFMA
// immediate and every structural zero vanishes.
// ============================================================================
namespace cgc {

__host__ __device__ constexpr double cfact(int n) {
  double r = 1.0;
  for (int i = 2; i <= n; ++i) r *= (double)i;
  return r;
}
__host__ __device__ constexpr double psign(int k) {
  return (k % 2 == 0) ? 1.0 : -1.0;
}
__host__ __device__ constexpr double csqrt(double x) {
  if (x <= 0.0) return 0.0;
  double r = x >= 1.0 ? x : 1.0;
  for (int i = 0; i < 200; ++i) {
    double nr = 0.5 * (r + x / r);
    if (nr == r) break;
    r = nr;
  }
  return r;
}

__host__ __device__ constexpr double w3jc(int l1, int l2, int l3, int m1,
                                          int m2) {
  const int m3 = -m1 - m2;
  if (m3 < -l3 || m3 > l3) return 0.0;
  const double tri = cfact(l1 + l2 - l3) * cfact(l1 - l2 + l3) *
                     cfact(-l1 + l2 + l3) / cfact(l1 + l2 + l3 + 1);
  const double pref =
      psign(l1 - l2 - m3) *
      csqrt(tri * cfact(l1 + m1) * cfact(l1 - m1) * cfact(l2 + m2) *
            cfact(l2 - m2) * cfact(l3 + m3) * cfact(l3 - m3));
  int t0 = 0;
  if (l2 - l3 - m1 > t0) t0 = l2 - l3 - m1;
  if (l1 - l3 + m2 > t0) t0 = l1 - l3 + m2;
  int t1 = l1 + l2 - l3;
  if (l1 - m1 < t1) t1 = l1 - m1;
  if (l2 + m2 < t1) t1 = l2 + m2;
  double s = 0.0;
  for (int t = t0; t <= t1; ++t) {
    s += psign(t) / (cfact(t) * cfact(l1 + l2 - l3 - t) * cfact(l1 - m1 - t) *
                     cfact(l2 + m2 - t) * cfact(l3 - l2 + m1 + t) *
                     cfact(l3 - l1 - m2 + t));
  }
  return pref * s;
}

struct URow {
  int n;
  int col[2];
  double re[2];
  double im[2];
};

__host__ __device__ constexpr URow urow(int l, int i) {
  URow r{};
  const double s2 = csqrt(0.5);
  const int mu = i - l;
  if (mu == 0) {
    r.n = 1;
    r.col[0] = l; r.re[0] = 1.0; r.im[0] = 0.0;
  } else if (mu > 0) {
    r.n = 2;
    r.col[0] = l + mu; r.re[0] = psign(mu) * s2; r.im[0] = 0.0;
    r.col[1] = l - mu; r.re[1] = s2;             r.im[1] = 0.0;
  } else {
    const int m = -mu;
    r.n = 2;
    r.col[0] = l - m; r.re[0] = 0.0; r.im[0] = s2;
    r.col[1] = l + m; r.re[1] = 0.0; r.im[1] = -psign(m) * s2;
  }
  return r;
}

__host__ __device__ constexpr double cg_real(int l1, int l2, int l3, int i,
                                             int j, int k) {
  const URow r1 = urow(l1, i);
  const URow r2 = urow(l2, j);
  const URow r3 = urow(l3, k);
  double acc = 0.0;
  for (int a = 0; a < r1.n; ++a)
    for (int b = 0; b < r2.n; ++b) {
      const int m1 = r1.col[a] - l1;
      const int m2 = r2.col[b] - l2;
      const int m3 = -m1 - m2;
      if (m3 < -l3 || m3 > l3) continue;
      const int cidx = m3 + l3;
      for (int c = 0; c < r3.n; ++c) {
        if (r3.col[c] != cidx) continue;
        const double re12 = r1.re[a] * r2.re[b] - r1.im[a] * r2.im[b];
        const double im12 = r1.re[a] * r2.im[b] + r1.im[a] * r2.re[b];
        const double rp = re12 * r3.re[c] - im12 * r3.im[c];
        if (rp != 0.0) acc += rp * w3jc(l1, l2, l3, m1, m2);
      }
    }
  return acc;
}

}  // namespace cgc

// ============================================================================
// Fully-unrolled tensor-product generators (FFMA-immediate, zeros elided).
// ============================================================================
template <int L1, int L2, int LO, int K, int I, int J>
__device__ __forceinline__ void add_term(float& a0, float& a1,
                                         const float* __restrict__ x,
                                         const float* __restrict__ y) {
  constexpr float c = (float)cgc::cg_real(L1, L2, LO, I, J, K);
  if constexpr (c > 1e-7f || c < -1e-7f) {
    if constexpr (((I + J) & 1) == 0)
      a0 += c * (x[I] * y[J]);
    else
      a1 += c * (x[I] * y[J]);
  }
}

template <int L1, int L2, int LO, int K, int I, int... Js>
__device__ __forceinline__ void add_row(float& a0, float& a1, const float* x,
                                        const float* y,
                                        std::integer_sequence<int, Js...>) {
  (add_term<L1, L2, LO, K, I, Js>(a0, a1, x, y), ...);
}

template <int L1, int L2, int LO, int K, int... Is>
__device__ __forceinline__ void add_all(float& a0, float& a1, const float* x,
                                        const float* y,
                                        std::integer_sequence<int, Is...>) {
  (add_row<L1, L2, LO, K, Is>(a0, a1, x, y,
                              std::make_integer_sequence<int, 2 * L2 + 1>{}),
   ...);
}

template <int L1, int L2, int LO, int K>
__device__ __forceinline__ float tp_k(const float* x, const float* y) {
  float a0 = 0.f, a1 = 0.f;
  add_all<L1, L2, LO, K>(a0, a1, x, y,
                         std::make_integer_sequence<int, 2 * L1 + 1>{});
  return a0 + a1;
}

// For one output component K of one path, compute t and fold the 4 copies'
// weighted contributions into acc[4][NK] (flattened).
template <int L1, int L2, int LO, int NK, int K>
__device__ __forceinline__ void fold_k(float* __restrict__ acc, const float* x,
                                       const float* y, float w0, float w1,
                                       float w2, float w3) {
  const float t = tp_k<L1, L2, LO, K>(x, y);
  acc[0 * NK + K] += w0 * t;
  acc[1 * NK + K] += w1 * t;
  acc[2 * NK + K] += w2 * t;
  acc[3 * NK + K] += w3 * t;
}

template <int L1, int L2, int LO, int NK, int... Ks>
__device__ __forceinline__ void fold_all_impl(
    float* acc, const float* x, const float* y, float w0, float w1, float w2,
    float w3, std::integer_sequence<int, Ks...>) {
  (fold_k<L1, L2, LO, NK, Ks>(acc, x, y, w0, w1, w2, w3), ...);
}
template <int L1, int L2, int LO>
__device__ __forceinline__ void fold_all(float* acc, const float* x,
                                         const float* y, float w0, float w1,
                                         float w2, float w3) {
  fold_all_impl<L1, L2, LO, 2 * LO + 1>(
      acc, x, y, w0, w1, w2, w3,
      std::make_integer_sequence<int, 2 * LO + 1>{});
}

// ============================================================================
// Kernel: 1 thread = 1 pixel. Phases:
//   A) halo tile (3 x 130 x 22, pad 23 -> conflict-free LDS) -> x[22], y[22]
//   B) pass1: all ell=4 outputs folded per-copy -> +residual -> smem staging
//      pass2: all ell=6 outputs likewise (tile memory reused as staging)
//   C) cooperative, fully-coalesced float4 stores from staging
// __launch_bounds__(128,4): cap regs at 128 -> 4 CTAs/SM (25% occ).
// ============================================================================
constexpr int TILE = 128;
constexpr int HALO = TILE + 2;
constexpr int SSTR = 130;  // staging row stride (floats); odd-ish vs banks

// pool serves as conv tile (3*130*23 = 8970 floats) then staging (88*130 =
// 11440 floats). 45760 B static shared.
__global__ __launch_bounds__(TILE, 4) void esc_kernel(
    const float* __restrict__ f4, const float* __restrict__ f6,
    const float* __restrict__ sw, const float* __restrict__ tw,
    float* __restrict__ out, int H, int W) {
  __shared__ float pool[88 * SSTR];

  const int tid = threadIdx.x;
  const int h = blockIdx.y;
  const int w0 = blockIdx.x * TILE;
  const bool valid = (w0 + tid) < W;

  // ---- phase A: cooperative halo load into tile view of pool
  for (int e = tid; e < 3 * HALO * 22; e += TILE) {
    int r = e / (HALO * 22);
    int rem = e - r * (HALO * 22);
    int tp = rem / 22;
    int ch = rem - tp * 22;
    int gh = h - 1 + r;
    gh = gh < 0 ? 0 : (gh >= H ? H - 1 : gh);
    int gw = w0 - 1 + tp;
    gw = gw < 0 ? 0 : (gw >= W ? W - 1 : gw);
    long nn = (long)gh * W + gw;
    pool[(r * HALO + tp) * 23 + ch] =
        (ch < 9) ? __ldg(f4 + nn * 9 + ch) : __ldg(f6 + nn * 13 + (ch - 9));
  }
  __syncthreads();

  float x[22], y[22];
  if (valid) {
    float s9[9];
#pragma unroll
    for (int i = 0; i < 9; ++i) s9[i] = __ldg(sw + i);
#pragma unroll
    for (int ch = 0; ch < 22; ++ch) {
      float a = 0.f;
#pragma unroll
      for (int dr = 0; dr < 3; ++dr)
#pragma unroll
        for (int dc = 0; dc < 3; ++dc)
          a += s9[dr * 3 + dc] * pool[(dr * HALO + tid + dc) * 23 + ch];
      y[ch] = a;
      x[ch] = pool[(1 * HALO + tid + 1) * 23 + ch];
    }
  }
  __syncthreads();  // tile dead; pool becomes staging

  const float A4 = 1.5f;                 // sqrt(9/4)
  const float A6 = 1.8027756377319946f;  // sqrt(13/4)

  if (valid) {
    // ---- pass 1: ell=4 outputs (36 accumulators)
    float acc4[36];
#pragma unroll
    for (int i = 0; i < 36; ++i) acc4[i] = 0.f;

    fold_all<4, 4, 4>(acc4, x, y, A4 * __ldg(tw + 0), A4 * __ldg(tw + 8),
                      A4 * __ldg(tw + 16), A4 * __ldg(tw + 24));
    fold_all<4, 6, 4>(acc4, x, y + 9, A4 * __ldg(tw + 1), A4 * __ldg(tw + 9),
                      A4 * __ldg(tw + 17), A4 * __ldg(tw + 25));
    fold_all<6, 4, 4>(acc4, x + 9, y, A4 * __ldg(tw + 2), A4 * __ldg(tw + 10),
                      A4 * __ldg(tw + 18), A4 * __ldg(tw + 26));
    fold_all<6, 6, 4>(acc4, x + 9, y + 9, A4 * __ldg(tw + 3),
                      A4 * __ldg(tw + 11), A4 * __ldg(tw + 19),
                      A4 * __ldg(tw + 27));

#pragma unroll
    for (int c = 0; c < 4; ++c)
#pragma unroll
      for (int k = 0; k < 9; ++k) {
        const int col = c * 22 + k;  // compile-time
        const float res = (col < 36) ? x[col % 9] : x[9 + (col - 36) % 13];
        pool[col * SSTR + tid] = acc4[c * 9 + k] + res;
      }

    // ---- pass 2: ell=6 outputs (52 accumulators)
    float acc6[52];
#pragma unroll
    for (int i = 0; i < 52; ++i) acc6[i] = 0.f;

    fold_all<4, 4, 6>(acc6, x, y, A6 * __ldg(tw + 4), A6 * __ldg(tw + 12),
                      A6 * __ldg(tw + 20), A6 * __ldg(tw + 28));
    fold_all<4, 6, 6>(acc6, x, y + 9, A6 * __ldg(tw + 5), A6 * __ldg(tw + 13),
                      A6 * __ldg(tw + 21), A6 * __ldg(tw + 29));
    fold_all<6, 4, 6>(acc6, x + 9, y, A6 * __ldg(tw + 6), A6 * __ldg(tw + 14),
                      A6 * __ldg(tw + 22), A6 * __ldg(tw + 30));
    fold_all<6, 6, 6>(acc6, x + 9, y + 9, A6 * __ldg(tw + 7),
                      A6 * __ldg(tw + 15), A6 * __ldg(tw + 23),
                      A6 * __ldg(tw + 31));

#pragma unroll
    for (int c = 0; c < 4; ++c)
#pragma unroll
      for (int k = 0; k < 13; ++k) {
        const int col = c * 22 + 9 + k;  // compile-time
        const float res = (col < 36) ? x[col % 9] : x[9 + (col - 36) % 13];
        pool[col * SSTR + tid] = acc6[c * 13 + k] + res;
      }
  }
  __syncthreads();

  // ---- phase C: cooperative coalesced float4 stores
  const long rowbase = (long)h * W;
  // region 1: f4_out block, 36 floats/px -> 9 float4 groups, 128*9 = 1152
#pragma unroll
  for (int it = 0; it < 9; ++it) {
    int e = it * TILE + tid;
    int px = e / 9;
    int g = e - px * 9;
    int wp = w0 + px;
    if (wp < W) {
      int s = g * 4;
      float4 v = make_float4(pool[(s + 0) * SSTR + px], pool[(s + 1) * SSTR + px],
                             pool[(s + 2) * SSTR + px], pool[(s + 3) * SSTR + px]);
      *reinterpret_cast<float4*>(out + (rowbase + wp) * 36 + s) = v;
    }
  }
  // region 2: f6_out block, 52 floats/px -> 13 float4 groups, 128*13 = 1664
  float* out2 = out + (long)H * W * 36;
#pragma unroll
  for (int it = 0; it < 13; ++it) {
    int e = it * TILE + tid;
    int px = e / 13;
    int g = e - px * 13;
    int wp = w0 + px;
    if (wp < W) {
      int s = 36 + g * 4;
      float4 v = make_float4(pool[(s + 0) * SSTR + px], pool[(s + 1) * SSTR + px],
                             pool[(s + 2) * SSTR + px], pool[(s + 3) * SSTR + px]);
      *reinterpret_cast<float4*>(out2 + (rowbase + wp) * 52 + g * 4) = v;
    }
  }
}

// ============================================================================
extern "C" void kernel_launch(void* const* d_in, const int* in_sizes, int n_in,
                              void* d_out, int out_size) {
  (void)n_in;
  (void)out_size;
  const float* f4 = (const float*)d_in[0];
  const float* f6 = (const float*)d_in[1];
  const float* sw = (const float*)d_in[2];
  const float* tw = (const float*)d_in[3];
  float* out = (float*)d_out;

  const long n = (long)in_sizes[0] / 9;  // HW
  int W = (int)(sqrt((double)n) + 0.5);  // H = W = 768 here
  if (W < 1) W = 1;
  int H = (int)(n / W);

  dim3 grid((W + TILE - 1) / TILE, H);
  esc_kernel<<<grid, TILE>>>(f4, f6, sw, tw, out, H, W);
}

// round 13
// speedup vs baseline: 1.0017x; 1.0017x over previous
#include <cuda_runtime.h>
#include <utility>
#include <math.h>

// ============================================================================
// Compile-time real-basis Wigner 3j (Clebsch-Gordan) coefficients.
// Evaluated by the C++ front end; every nonzero entry becomes an FFMA
// immediate and every structural zero vanishes.
// ============================================================================
namespace cgc {

__host__ __device__ constexpr double cfact(int n) {
  double r = 1.0;
  for (int i = 2; i <= n; ++i) r *= (double)i;
  return r;
}
__host__ __device__ constexpr double psign(int k) {
  return (k % 2 == 0) ? 1.0 : -1.0;
}
__host__ __device__ constexpr double csqrt(double x) {
  if (x <= 0.0) return 0.0;
  double r = x >= 1.0 ? x : 1.0;
  for (int i = 0; i < 200; ++i) {
    double nr = 0.5 * (r + x / r);
    if (nr == r) break;
    r = nr;
  }
  return r;
}

__host__ __device__ constexpr double w3jc(int l1, int l2, int l3, int m1,
                                          int m2) {
  const int m3 = -m1 - m2;
  if (m3 < -l3 || m3 > l3) return 0.0;
  const double tri = cfact(l1 + l2 - l3) * cfact(l1 - l2 + l3) *
                     cfact(-l1 + l2 + l3) / cfact(l1 + l2 + l3 + 1);
  const double pref =
      psign(l1 - l2 - m3) *
      csqrt(tri * cfact(l1 + m1) * cfact(l1 - m1) * cfact(l2 + m2) *
            cfact(l2 - m2) * cfact(l3 + m3) * cfact(l3 - m3));
  int t0 = 0;
  if (l2 - l3 - m1 > t0) t0 = l2 - l3 - m1;
  if (l1 - l3 + m2 > t0) t0 = l1 - l3 + m2;
  int t1 = l1 + l2 - l3;
  if (l1 - m1 < t1) t1 = l1 - m1;
  if (l2 + m2 < t1) t1 = l2 + m2;
  double s = 0.0;
  for (int t = t0; t <= t1; ++t) {
    s += psign(t) / (cfact(t) * cfact(l1 + l2 - l3 - t) * cfact(l1 - m1 - t) *
                     cfact(l2 + m2 - t) * cfact(l3 - l2 + m1 + t) *
                     cfact(l3 - l1 - m2 + t));
  }
  return pref * s;
}

struct URow {
  int n;
  int col[2];
  double re[2];
  double im[2];
};

__host__ __device__ constexpr URow urow(int l, int i) {
  URow r{};
  const double s2 = csqrt(0.5);
  const int mu = i - l;
  if (mu == 0) {
    r.n = 1;
    r.col[0] = l; r.re[0] = 1.0; r.im[0] = 0.0;
  } else if (mu > 0) {
    r.n = 2;
    r.col[0] = l + mu; r.re[0] = psign(mu) * s2; r.im[0] = 0.0;
    r.col[1] = l - mu; r.re[1] = s2;             r.im[1] = 0.0;
  } else {
    const int m = -mu;
    r.n = 2;
    r.col[0] = l - m; r.re[0] = 0.0; r.im[0] = s2;
    r.col[1] = l + m; r.re[1] = 0.0; r.im[1] = -psign(m) * s2;
  }
  return r;
}

__host__ __device__ constexpr double cg_real(int l1, int l2, int l3, int i,
                                             int j, int k) {
  const URow r1 = urow(l1, i);
  const URow r2 = urow(l2, j);
  const URow r3 = urow(l3, k);
  double acc = 0.0;
  for (int a = 0; a < r1.n; ++a)
    for (int b = 0; b < r2.n; ++b) {
      const int m1 = r1.col[a] - l1;
      const int m2 = r2.col[b] - l2;
      const int m3 = -m1 - m2;
      if (m3 < -l3 || m3 > l3) continue;
      const int cidx = m3 + l3;
      for (int c = 0; c < r3.n; ++c) {
        if (r3.col[c] != cidx) continue;
        const double re12 = r1.re[a] * r2.re[b] - r1.im[a] * r2.im[b];
        const double im12 = r1.re[a] * r2.im[b] + r1.im[a] * r2.re[b];
        const double rp = re12 * r3.re[c] - im12 * r3.im[c];
        if (rp != 0.0) acc += rp * w3jc(l1, l2, l3, m1, m2);
      }
    }
  return acc;
}

}  // namespace cgc

// ============================================================================
// Fully-unrolled tensor-product generators (FFMA-immediate, zeros elided).
// ============================================================================
template <int L1, int L2, int LO, int K, int I, int J>
__device__ __forceinline__ void add_term(float& a0, float& a1,
                                         const float* __restrict__ x,
                                         const float* __restrict__ y) {
  constexpr float c = (float)cgc::cg_real(L1, L2, LO, I, J, K);
  if constexpr (c > 1e-7f || c < -1e-7f) {
    if constexpr (((I + J) & 1) == 0)
      a0 += c * (x[I] * y[J]);
    else
      a1 += c * (x[I] * y[J]);
  }
}

template <int L1, int L2, int LO, int K, int I, int... Js>
__device__ __forceinline__ void add_row(float& a0, float& a1, const float* x,
                                        const float* y,
                                        std::integer_sequence<int, Js...>) {
  (add_term<L1, L2, LO, K, I, Js>(a0, a1, x, y), ...);
}

template <int L1, int L2, int LO, int K, int... Is>
__device__ __forceinline__ void add_all(float& a0, float& a1, const float* x,
                                        const float* y,
                                        std::integer_sequence<int, Is...>) {
  (add_row<L1, L2, LO, K, Is>(a0, a1, x, y,
                              std::make_integer_sequence<int, 2 * L2 + 1>{}),
   ...);
}

template <int L1, int L2, int LO, int K>
__device__ __forceinline__ float tp_k(const float* x, const float* y) {
  float a0 = 0.f, a1 = 0.f;
  add_all<L1, L2, LO, K>(a0, a1, x, y,
                         std::make_integer_sequence<int, 2 * L1 + 1>{});
  return a0 + a1;
}

// For one output component K of one path, compute t and fold the 4 copies'
// weighted contributions into acc[4][NK] (flattened).
template <int L1, int L2, int LO, int NK, int K>
__device__ __forceinline__ void fold_k(float* __restrict__ acc, const float* x,
                                       const float* y, float w0, float w1,
                                       float w2, float w3) {
  const float t = tp_k<L1, L2, LO, K>(x, y);
  acc[0 * NK + K] += w0 * t;
  acc[1 * NK + K] += w1 * t;
  acc[2 * NK + K] += w2 * t;
  acc[3 * NK + K] += w3 * t;
}

template <int L1, int L2, int LO, int NK, int... Ks>
__device__ __forceinline__ void fold_all_impl(
    float* acc, const float* x, const float* y, float w0, float w1, float w2,
    float w3, std::integer_sequence<int, Ks...>) {
  (fold_k<L1, L2, LO, NK, Ks>(acc, x, y, w0, w1, w2, w3), ...);
}
template <int L1, int L2, int LO>
__device__ __forceinline__ void fold_all(float* acc, const float* x,
                                         const float* y, float w0, float w1,
                                         float w2, float w3) {
  fold_all_impl<L1, L2, LO, 2 * LO + 1>(
      acc, x, y, w0, w1, w2, w3,
      std::make_integer_sequence<int, 2 * LO + 1>{});
}

// ============================================================================
// Kernel: 1 thread = 1 pixel. Phases:
//   A) halo tile (3 x 130 x 22, pad 23 -> conflict-free LDS) -> x[22], y[22]
//   B) pass1: all ell=4 outputs folded per-copy -> +residual -> smem staging
//      pass2: all ell=6 outputs likewise (tile memory reused as staging)
//   C) cooperative, fully-coalesced float4 stores from staging
// __launch_bounds__(128,4): cap regs at 128 -> 4 CTAs/SM (25% occ).
// ============================================================================
constexpr int TILE = 128;
constexpr int HALO = TILE + 2;
constexpr int SSTR = 130;  // staging row stride (floats); odd-ish vs banks

// pool serves as conv tile (3*130*23 = 8970 floats) then staging (88*130 =
// 11440 floats). 45760 B static shared.
__global__ __launch_bounds__(TILE, 4) void esc_kernel(
    const float* __restrict__ f4, const float* __restrict__ f6,
    const float* __restrict__ sw, const float* __restrict__ tw,
    float* __restrict__ out, int H, int W) {
  __shared__ float pool[88 * SSTR];

  const int tid = threadIdx.x;
  const int h = blockIdx.y;
  const int w0 = blockIdx.x * TILE;
  const bool valid = (w0 + tid) < W;

  // ---- phase A: cooperative halo load into tile view of pool
  for (int e = tid; e < 3 * HALO * 22; e += TILE) {
    int r = e / (HALO * 22);
    int rem = e - r * (HALO * 22);
    int tp = rem / 22;
    int ch = rem - tp * 22;
    int gh = h - 1 + r;
    gh = gh < 0 ? 0 : (gh >= H ? H - 1 : gh);
    int gw = w0 - 1 + tp;
    gw = gw < 0 ? 0 : (gw >= W ? W - 1 : gw);
    long nn = (long)gh * W + gw;
    pool[(r * HALO + tp) * 23 + ch] =
        (ch < 9) ? __ldg(f4 + nn * 9 + ch) : __ldg(f6 + nn * 13 + (ch - 9));
  }
  __syncthreads();

  float x[22], y[22];
  if (valid) {
    float s9[9];
#pragma unroll
    for (int i = 0; i < 9; ++i) s9[i] = __ldg(sw + i);
#pragma unroll
    for (int ch = 0; ch < 22; ++ch) {
      float a = 0.f;
#pragma unroll
      for (int dr = 0; dr < 3; ++dr)
#pragma unroll
        for (int dc = 0; dc < 3; ++dc)
          a += s9[dr * 3 + dc] * pool[(dr * HALO + tid + dc) * 23 + ch];
      y[ch] = a;
      x[ch] = pool[(1 * HALO + tid + 1) * 23 + ch];
    }
  }
  __syncthreads();  // tile dead; pool becomes staging

  const float A4 = 1.5f;                 // sqrt(9/4)
  const float A6 = 1.8027756377319946f;  // sqrt(13/4)

  if (valid) {
    // ---- pass 1: ell=4 outputs (36 accumulators)
    float acc4[36];
#pragma unroll
    for (int i = 0; i < 36; ++i) acc4[i] = 0.f;

    fold_all<4, 4, 4>(acc4, x, y, A4 * __ldg(tw + 0), A4 * __ldg(tw + 8),
                      A4 * __ldg(tw + 16), A4 * __ldg(tw + 24));
    fold_all<4, 6, 4>(acc4, x, y + 9, A4 * __ldg(tw + 1), A4 * __ldg(tw + 9),
                      A4 * __ldg(tw + 17), A4 * __ldg(tw + 25));
    fold_all<6, 4, 4>(acc4, x + 9, y, A4 * __ldg(tw + 2), A4 * __ldg(tw + 10),
                      A4 * __ldg(tw + 18), A4 * __ldg(tw + 26));
    fold_all<6, 6, 4>(acc4, x + 9, y + 9, A4 * __ldg(tw + 3),
                      A4 * __ldg(tw + 11), A4 * __ldg(tw + 19),
                      A4 * __ldg(tw + 27));

#pragma unroll
    for (int c = 0; c < 4; ++c)
#pragma unroll
      for (int k = 0; k < 9; ++k) {
        const int col = c * 22 + k;  // compile-time
        const float res = (col < 36) ? x[col % 9] : x[9 + (col - 36) % 13];
        pool[col * SSTR + tid] = acc4[c * 9 + k] + res;
      }

    // ---- pass 2: ell=6 outputs (52 accumulators)
    float acc6[52];
#pragma unroll
    for (int i = 0; i < 52; ++i) acc6[i] = 0.f;

    fold_all<4, 4, 6>(acc6, x, y, A6 * __ldg(tw + 4), A6 * __ldg(tw + 12),
                      A6 * __ldg(tw + 20), A6 * __ldg(tw + 28));
    fold_all<4, 6, 6>(acc6, x, y + 9, A6 * __ldg(tw + 5), A6 * __ldg(tw + 13),
                      A6 * __ldg(tw + 21), A6 * __ldg(tw + 29));
    fold_all<6, 4, 6>(acc6, x + 9, y, A6 * __ldg(tw + 6), A6 * __ldg(tw + 14),
                      A6 * __ldg(tw + 22), A6 * __ldg(tw + 30));
    fold_all<6, 6, 6>(acc6, x + 9, y + 9, A6 * __ldg(tw + 7),
                      A6 * __ldg(tw + 15), A6 * __ldg(tw + 23),
                      A6 * __ldg(tw + 31));

#pragma unroll
    for (int c = 0; c < 4; ++c)
#pragma unroll
      for (int k = 0; k < 13; ++k) {
        const int col = c * 22 + 9 + k;  // compile-time
        const float res = (col < 36) ? x[col % 9] : x[9 + (col - 36) % 13];
        pool[col * SSTR + tid] = acc6[c * 13 + k] + res;
      }
  }
  __syncthreads();

  // ---- phase C: cooperative coalesced float4 stores
  const long rowbase = (long)h * W;
  // region 1: f4_out block, 36 floats/px -> 9 float4 groups, 128*9 = 1152
#pragma unroll
  for (int it = 0; it < 9; ++it) {
    int e = it * TILE + tid;
    int px = e / 9;
    int g = e - px * 9;
    int wp = w0 + px;
    if (wp < W) {
      int s = g * 4;
      float4 v = make_float4(pool[(s + 0) * SSTR + px], pool[(s + 1) * SSTR + px],
                             pool[(s + 2) * SSTR + px], pool[(s + 3) * SSTR + px]);
      *reinterpret_cast<float4*>(out + (rowbase + wp) * 36 + s) = v;
    }
  }
  // region 2: f6_out block, 52 floats/px -> 13 float4 groups, 128*13 = 1664
  float* out2 = out + (long)H * W * 36;
#pragma unroll
  for (int it = 0; it < 13; ++it) {
    int e = it * TILE + tid;
    int px = e / 13;
    int g = e - px * 13;
    int wp = w0 + px;
    if (wp < W) {
      int s = 36 + g * 4;
      float4 v = make_float4(pool[(s + 0) * SSTR + px], pool[(s + 1) * SSTR + px],
                             pool[(s + 2) * SSTR + px], pool[(s + 3) * SSTR + px]);
      *reinterpret_cast<float4*>(out2 + (rowbase + wp) * 52 + g * 4) = v;
    }
  }
}

// ============================================================================
extern "C" void kernel_launch(void* const* d_in, const int* in_sizes, int n_in,
                              void* d_out, int out_size) {
  (void)n_in;
  (void)out_size;
  const float* f4 = (const float*)d_in[0];
  const float* f6 = (const float*)d_in[1];
  const float* sw = (const float*)d_in[2];
  const float* tw = (const float*)d_in[3];
  float* out = (float*)d_out;

  const long n = (long)in_sizes[0] / 9;  // HW
  int W = (int)(sqrt((double)n) + 0.5);  // H = W = 768 here
  if (W < 1) W = 1;
  int H = (int)(n / W);

  dim3 grid((W + TILE - 1) / TILE, H);
  esc_kernel<<<grid, TILE>>>(f4, f6, sw, tw, out, H, W);
}

// round 14
// speedup vs baseline: 1.4441x; 1.4416x over previous
#include <cuda_runtime.h>
#include <utility>
#include <math.h>

// ============================================================================
// Compile-time real-basis Wigner 3j (Clebsch-Gordan) coefficients.
// ============================================================================
namespace cgc {

__host__ __device__ constexpr double cfact(int n) {
  double r = 1.0;
  for (int i = 2; i <= n; ++i) r *= (double)i;
  return r;
}
__host__ __device__ constexpr double psign(int k) {
  return (k % 2 == 0) ? 1.0 : -1.0;
}
__host__ __device__ constexpr double csqrt(double x) {
  if (x <= 0.0) return 0.0;
  double r = x >= 1.0 ? x : 1.0;
  for (int i = 0; i < 200; ++i) {
    double nr = 0.5 * (r + x / r);
    if (nr == r) break;
    r = nr;
  }
  return r;
}

__host__ __device__ constexpr double w3jc(int l1, int l2, int l3, int m1,
                                          int m2) {
  const int m3 = -m1 - m2;
  if (m3 < -l3 || m3 > l3) return 0.0;
  const double tri = cfact(l1 + l2 - l3) * cfact(l1 - l2 + l3) *
                     cfact(-l1 + l2 + l3) / cfact(l1 + l2 + l3 + 1);
  const double pref =
      psign(l1 - l2 - m3) *
      csqrt(tri * cfact(l1 + m1) * cfact(l1 - m1) * cfact(l2 + m2) *
            cfact(l2 - m2) * cfact(l3 + m3) * cfact(l3 - m3));
  int t0 = 0;
  if (l2 - l3 - m1 > t0) t0 = l2 - l3 - m1;
  if (l1 - l3 + m2 > t0) t0 = l1 - l3 + m2;
  int t1 = l1 + l2 - l3;
  if (l1 - m1 < t1) t1 = l1 - m1;
  if (l2 + m2 < t1) t1 = l2 + m2;
  double s = 0.0;
  for (int t = t0; t <= t1; ++t) {
    s += psign(t) / (cfact(t) * cfact(l1 + l2 - l3 - t) * cfact(l1 - m1 - t) *
                     cfact(l2 + m2 - t) * cfact(l3 - l2 + m1 + t) *
                     cfact(l3 - l1 - m2 + t));
  }
  return pref * s;
}

struct URow {
  int n;
  int col[2];
  double re[2];
  double im[2];
};

__host__ __device__ constexpr URow urow(int l, int i) {
  URow r{};
  const double s2 = csqrt(0.5);
  const int mu = i - l;
  if (mu == 0) {
    r.n = 1;
    r.col[0] = l; r.re[0] = 1.0; r.im[0] = 0.0;
  } else if (mu > 0) {
    r.n = 2;
    r.col[0] = l + mu; r.re[0] = psign(mu) * s2; r.im[0] = 0.0;
    r.col[1] = l - mu; r.re[1] = s2;             r.im[1] = 0.0;
  } else {
    const int m = -mu;
    r.n = 2;
    r.col[0] = l - m; r.re[0] = 0.0; r.im[0] = s2;
    r.col[1] = l + m; r.re[1] = 0.0; r.im[1] = -psign(m) * s2;
  }
  return r;
}

__host__ __device__ constexpr double cg_real(int l1, int l2, int l3, int i,
                                             int j, int k) {
  const URow r1 = urow(l1, i);
  const URow r2 = urow(l2, j);
  const URow r3 = urow(l3, k);
  double acc = 0.0;
  for (int a = 0; a < r1.n; ++a)
    for (int b = 0; b < r2.n; ++b) {
      const int m1 = r1.col[a] - l1;
      const int m2 = r2.col[b] - l2;
      const int m3 = -m1 - m2;
      if (m3 < -l3 || m3 > l3) continue;
      const int cidx = m3 + l3;
      for (int c = 0; c < r3.n; ++c) {
        if (r3.col[c] != cidx) continue;
        const double re12 = r1.re[a] * r2.re[b] - r1.im[a] * r2.im[b];
        const double im12 = r1.re[a] * r2.im[b] + r1.im[a] * r2.re[b];
        const double rp = re12 * r3.re[c] - im12 * r3.im[c];
        if (rp != 0.0) acc += rp * w3jc(l1, l2, l3, m1, m2);
      }
    }
  return acc;
}

}  // namespace cgc

// ============================================================================
// Fully-unrolled tensor-product component (FFMA-immediate, zeros elided).
// ============================================================================
template <int L1, int L2, int LO, int K, int I, int J>
__device__ __forceinline__ void add_term(float& a0, float& a1,
                                         const float* __restrict__ x,
                                         const float* __restrict__ y) {
  constexpr float c = (float)cgc::cg_real(L1, L2, LO, I, J, K);
  if constexpr (c > 1e-7f || c < -1e-7f) {
    if constexpr (((I + J) & 1) == 0)
      a0 += c * (x[I] * y[J]);
    else
      a1 += c * (x[I] * y[J]);
  }
}

template <int L1, int L2, int LO, int K, int I, int... Js>
__device__ __forceinline__ void add_row(float& a0, float& a1, const float* x,
                                        const float* y,
                                        std::integer_sequence<int, Js...>) {
  (add_term<L1, L2, LO, K, I, Js>(a0, a1, x, y), ...);
}

template <int L1, int L2, int LO, int K, int... Is>
__device__ __forceinline__ void add_all(float& a0, float& a1, const float* x,
                                        const float* y,
                                        std::integer_sequence<int, Is...>) {
  (add_row<L1, L2, LO, K, Is>(a0, a1, x, y,
                              std::make_integer_sequence<int, 2 * L2 + 1>{}),
   ...);
}

template <int L1, int L2, int LO, int K>
__device__ __forceinline__ float tp_k(const float* x, const float* y) {
  float a0 = 0.f, a1 = 0.f;
  add_all<L1, L2, LO, K>(a0, a1, x, y,
                         std::make_integer_sequence<int, 2 * L1 + 1>{});
  return a0 + a1;
}

// ============================================================================
// Kernel constants
// ============================================================================
constexpr int TILE = 128;
constexpr int HALO = TILE + 2;
constexpr int SSTR = 130;  // staging row stride (floats)

// compile-time residual selector for output column col (0..87):
// cols [0,36) carry f4 residual x[col%9]; cols [36,88) carry x[9+(col-36)%13]
template <int COL>
__device__ __forceinline__ float res_of(const float* __restrict__ x) {
  if constexpr (COL < 36)
    return x[COL % 9];
  else
    return x[9 + (COL - 36) % 13];
}

// Emit one k-group: lo=6 component K6 (always valid, 0..12) and lo=4
// component K4 = K6-2 when in range. Computes the 4 path t-values once,
// folds all 4 copies' weighted outputs + residual, stores straight to the
// smem staging buffer. No persistent accumulators.
template <int G>
__device__ __forceinline__ void emit_group(float* __restrict__ pool, int tid,
                                           const float* __restrict__ x,
                                           const float* __restrict__ y,
                                           const float* __restrict__ w4,
                                           const float* __restrict__ w6) {
  constexpr int K6 = G;
  constexpr int K4 = G - 2;

  if constexpr (K4 >= 0 && K4 < 9) {
    const float t0 = tp_k<4, 4, 4, K4>(x, y);
    const float t1 = tp_k<4, 6, 4, K4>(x, y + 9);
    const float t2 = tp_k<6, 4, 4, K4>(x + 9, y);
    const float t3 = tp_k<6, 6, 4, K4>(x + 9, y + 9);
#pragma unroll
    for (int c = 0; c < 4; ++c) {
      constexpr int base = K4;  // col = c*22 + K4
      float v = w4[c * 4 + 0] * t0 + w4[c * 4 + 1] * t1 +
                w4[c * 4 + 2] * t2 + w4[c * 4 + 3] * t3;
      if (c == 0) v += res_of<base + 0 * 22>(x);
      if (c == 1) v += res_of<base + 1 * 22>(x);
      if (c == 2) v += res_of<base + 2 * 22>(x);
      if (c == 3) v += res_of<base + 3 * 22>(x);
      pool[(c * 22 + K4) * SSTR + tid] = v;
    }
  }

  {
    const float s0 = tp_k<4, 4, 6, K6>(x, y);
    const float s1 = tp_k<4, 6, 6, K6>(x, y + 9);
    const float s2 = tp_k<6, 4, 6, K6>(x + 9, y);
    const float s3 = tp_k<6, 6, 6, K6>(x + 9, y + 9);
#pragma unroll
    for (int c = 0; c < 4; ++c) {
      constexpr int base = 9 + K6;  // col = c*22 + 9 + K6
      float v = w6[c * 4 + 0] * s0 + w6[c * 4 + 1] * s1 +
                w6[c * 4 + 2] * s2 + w6[c * 4 + 3] * s3;
      if (c == 0) v += res_of<base + 0 * 22>(x);
      if (c == 1) v += res_of<base + 1 * 22>(x);
      if (c == 2) v += res_of<base + 2 * 22>(x);
      if (c == 3) v += res_of<base + 3 * 22>(x);
      pool[(c * 22 + 9 + K6) * SSTR + tid] = v;
    }
  }
}

template <int... Gs>
__device__ __forceinline__ void emit_all(float* pool, int tid, const float* x,
                                         const float* y, const float* w4,
                                         const float* w6,
                                         std::integer_sequence<int, Gs...>) {
  (emit_group<Gs>(pool, tid, x, y, w4, w6), ...);
}

// ============================================================================
// Main kernel: 1 thread = 1 pixel (streamed outputs, smem staging, coalesced
// float4 stores). launch_bounds(128,4): 128-reg cap, now safe because no
// 88-wide accumulator array exists.
// ============================================================================
__global__ __launch_bounds__(TILE, 4) void esc_kernel(
    const float* __restrict__ f4, const float* __restrict__ f6,
    const float* __restrict__ sw, const float* __restrict__ tw,
    float* __restrict__ out, int H, int W) {
  __shared__ float pool[88 * SSTR];

  const int tid = threadIdx.x;
  const int h = blockIdx.y;
  const int w0 = blockIdx.x * TILE;
  const bool valid = (w0 + tid) < W;

  // ---- phase A: cooperative halo load into tile view of pool
  for (int e = tid; e < 3 * HALO * 22; e += TILE) {
    int r = e / (HALO * 22);
    int rem = e - r * (HALO * 22);
    int tp = rem / 22;
    int ch = rem - tp * 22;
    int gh = h - 1 + r;
    gh = gh < 0 ? 0 : (gh >= H ? H - 1 : gh);
    int gw = w0 - 1 + tp;
    gw = gw < 0 ? 0 : (gw >= W ? W - 1 : gw);
    long nn = (long)gh * W + gw;
    pool[(r * HALO + tp) * 23 + ch] =
        (ch < 9) ? __ldg(f4 + nn * 9 + ch) : __ldg(f6 + nn * 13 + (ch - 9));
  }
  __syncthreads();

  float x[22], y[22];
  if (valid) {
    float s9[9];
#pragma unroll
    for (int i = 0; i < 9; ++i) s9[i] = __ldg(sw + i);
#pragma unroll
    for (int ch = 0; ch < 22; ++ch) {
      float a = 0.f;
#pragma unroll
      for (int dr = 0; dr < 3; ++dr)
#pragma unroll
        for (int dc = 0; dc < 3; ++dc)
          a += s9[dr * 3 + dc] * pool[(dr * HALO + tid + dc) * 23 + ch];
      y[ch] = a;
      x[ch] = pool[(1 * HALO + tid + 1) * 23 + ch];
    }
  }
  __syncthreads();  // tile dead; pool becomes staging

  if (valid) {
    const float A4 = 1.5f;                 // sqrt(9/4)
    const float A6 = 1.8027756377319946f;  // sqrt(13/4)
    float w4[16], w6[16];
#pragma unroll
    for (int c = 0; c < 4; ++c)
#pragma unroll
      for (int p = 0; p < 4; ++p) {
        w4[c * 4 + p] = A4 * __ldg(tw + c * 8 + p);
        w6[c * 4 + p] = A6 * __ldg(tw + c * 8 + 4 + p);
      }

    emit_all(pool, tid, x, y, w4, w6,
             std::make_integer_sequence<int, 13>{});
  }
  __syncthreads();

  // ---- phase C: cooperative coalesced float4 stores
  const long rowbase = (long)h * W;
  // region 1: 36 floats/px -> 9 float4 groups
#pragma unroll
  for (int it = 0; it < 9; ++it) {
    int e = it * TILE + tid;
    int px = e / 9;
    int g = e - px * 9;
    int wp = w0 + px;
    if (wp < W) {
      int s = g * 4;
      float4 v =
          make_float4(pool[(s + 0) * SSTR + px], pool[(s + 1) * SSTR + px],
                      pool[(s + 2) * SSTR + px], pool[(s + 3) * SSTR + px]);
      *reinterpret_cast<float4*>(out + (rowbase + wp) * 36 + s) = v;
    }
  }
  // region 2: 52 floats/px -> 13 float4 groups
  float* out2 = out + (long)H * W * 36;
#pragma unroll
  for (int it = 0; it < 13; ++it) {
    int e = it * TILE + tid;
    int px = e / 13;
    int g = e - px * 13;
    int wp = w0 + px;
    if (wp < W) {
      int s = 36 + g * 4;
      float4 v =
          make_float4(pool[(s + 0) * SSTR + px], pool[(s + 1) * SSTR + px],
                      pool[(s + 2) * SSTR + px], pool[(s + 3) * SSTR + px]);
      *reinterpret_cast<float4*>(out2 + (rowbase + wp) * 52 + g * 4) = v;
    }
  }
}

// ============================================================================
extern "C" void kernel_launch(void* const* d_in, const int* in_sizes, int n_in,
                              void* d_out, int out_size) {
  (void)n_in;
  (void)out_size;
  const float* f4 = (const float*)d_in[0];
  const float* f6 = (const float*)d_in[1];
  const float* sw = (const float*)d_in[2];
  const float* tw = (const float*)d_in[3];
  float* out = (float*)d_out;

  const long n = (long)in_sizes[0] / 9;  // HW
  int W = (int)(sqrt((double)n) + 0.5);  // H = W = 768 here
  if (W < 1) W = 1;
  int H = (int)(n / W);

  dim3 grid((W + TILE - 1) / TILE, H);
  esc_kernel<<<grid, TILE>>>(f4, f6, sw, tw, out, H, W);
}

// round 15
// speedup vs baseline: 2.7485x; 1.9033x over previous
#include <cuda_runtime.h>
#include <utility>
#include <math.h>

// ============================================================================
// Compile-time real-basis Wigner 3j (Clebsch-Gordan) coefficients.
// ============================================================================
namespace cgc {

__host__ __device__ constexpr double cfact(int n) {
  double r = 1.0;
  for (int i = 2; i <= n; ++i) r *= (double)i;
  return r;
}
__host__ __device__ constexpr double psign(int k) {
  return (k % 2 == 0) ? 1.0 : -1.0;
}
__host__ __device__ constexpr double csqrt(double x) {
  if (x <= 0.0) return 0.0;
  double r = x >= 1.0 ? x : 1.0;
  for (int i = 0; i < 200; ++i) {
    double nr = 0.5 * (r + x / r);
    if (nr == r) break;
    r = nr;
  }
  return r;
}

__host__ __device__ constexpr double w3jc(int l1, int l2, int l3, int m1,
                                          int m2) {
  const int m3 = -m1 - m2;
  if (m3 < -l3 || m3 > l3) return 0.0;
  const double tri = cfact(l1 + l2 - l3) * cfact(l1 - l2 + l3) *
                     cfact(-l1 + l2 + l3) / cfact(l1 + l2 + l3 + 1);
  const double pref =
      psign(l1 - l2 - m3) *
      csqrt(tri * cfact(l1 + m1) * cfact(l1 - m1) * cfact(l2 + m2) *
            cfact(l2 - m2) * cfact(l3 + m3) * cfact(l3 - m3));
  int t0 = 0;
  if (l2 - l3 - m1 > t0) t0 = l2 - l3 - m1;
  if (l1 - l3 + m2 > t0) t0 = l1 - l3 + m2;
  int t1 = l1 + l2 - l3;
  if (l1 - m1 < t1) t1 = l1 - m1;
  if (l2 + m2 < t1) t1 = l2 + m2;
  double s = 0.0;
  for (int t = t0; t <= t1; ++t) {
    s += psign(t) / (cfact(t) * cfact(l1 + l2 - l3 - t) * cfact(l1 - m1 - t) *
                     cfact(l2 + m2 - t) * cfact(l3 - l2 + m1 + t) *
                     cfact(l3 - l1 - m2 + t));
  }
  return pref * s;
}

struct URow {
  int n;
  int col[2];
  double re[2];
  double im[2];
};

__host__ __device__ constexpr URow urow(int l, int i) {
  URow r{};
  const double s2 = csqrt(0.5);
  const int mu = i - l;
  if (mu == 0) {
    r.n = 1;
    r.col[0] = l; r.re[0] = 1.0; r.im[0] = 0.0;
  } else if (mu > 0) {
    r.n = 2;
    r.col[0] = l + mu; r.re[0] = psign(mu) * s2; r.im[0] = 0.0;
    r.col[1] = l - mu; r.re[1] = s2;             r.im[1] = 0.0;
  } else {
    const int m = -mu;
    r.n = 2;
    r.col[0] = l - m; r.re[0] = 0.0; r.im[0] = s2;
    r.col[1] = l + m; r.re[1] = 0.0; r.im[1] = -psign(m) * s2;
  }
  return r;
}

__host__ __device__ constexpr double cg_real(int l1, int l2, int l3, int i,
                                             int j, int k) {
  const URow r1 = urow(l1, i);
  const URow r2 = urow(l2, j);
  const URow r3 = urow(l3, k);
  double acc = 0.0;
  for (int a = 0; a < r1.n; ++a)
    for (int b = 0; b < r2.n; ++b) {
      const int m1 = r1.col[a] - l1;
      const int m2 = r2.col[b] - l2;
      const int m3 = -m1 - m2;
      if (m3 < -l3 || m3 > l3) continue;
      const int cidx = m3 + l3;
      for (int c = 0; c < r3.n; ++c) {
        if (r3.col[c] != cidx) continue;
        const double re12 = r1.re[a] * r2.re[b] - r1.im[a] * r2.im[b];
        const double im12 = r1.re[a] * r2.im[b] + r1.im[a] * r2.re[b];
        const double rp = re12 * r3.re[c] - im12 * r3.im[c];
        if (rp != 0.0) acc += rp * w3jc(l1, l2, l3, m1, m2);
      }
    }
  return acc;
}

}  // namespace cgc

// ============================================================================
// Fully-unrolled tensor-product component (FFMA-immediate, zeros elided).
// ============================================================================
template <int L1, int L2, int LO, int K, int I, int J>
__device__ __forceinline__ void add_term(float& a0, float& a1,
                                         const float* __restrict__ x,
                                         const float* __restrict__ y) {
  constexpr float c = (float)cgc::cg_real(L1, L2, LO, I, J, K);
  if constexpr (c > 1e-7f || c < -1e-7f) {
    if constexpr (((I + J) & 1) == 0)
      a0 += c * (x[I] * y[J]);
    else
      a1 += c * (x[I] * y[J]);
  }
}

template <int L1, int L2, int LO, int K, int I, int... Js>
__device__ __forceinline__ void add_row(float& a0, float& a1, const float* x,
                                        const float* y,
                                        std::integer_sequence<int, Js...>) {
  (add_term<L1, L2, LO, K, I, Js>(a0, a1, x, y), ...);
}

template <int L1, int L2, int LO, int K, int... Is>
__device__ __forceinline__ void add_all(float& a0, float& a1, const float* x,
                                        const float* y,
                                        std::integer_sequence<int, Is...>) {
  (add_row<L1, L2, LO, K, Is>(a0, a1, x, y,
                              std::make_integer_sequence<int, 2 * L2 + 1>{}),
   ...);
}

template <int L1, int L2, int LO, int K>
__device__ __forceinline__ float tp_k(const float* x, const float* y) {
  float a0 = 0.f, a1 = 0.f;
  add_all<L1, L2, LO, K>(a0, a1, x, y,
                         std::make_integer_sequence<int, 2 * L1 + 1>{});
  return a0 + a1;
}

// ============================================================================
// Kernel constants / layout
// ============================================================================
constexpr int TILE = 128;
constexpr int NPX = TILE + 2;   // 130 halo pixels per row
constexpr int SSTR = 129;       // staging stride (odd -> conflict-free)
// conv tiles (packed, same layout as global): f4 plane 3*130*9 = 3510 floats,
// f6 plane 3*130*13 = 5070 floats, total 8580. staging needs 88*129 = 11352.
constexpr int F6OFF = 3 * NPX * 9;  // 3510
constexpr int POOLN = 88 * SSTR;    // 11352 floats = 45408 B

// compile-time residual selector for output column col (0..87)
template <int COL>
__device__ __forceinline__ float res_of(const float* __restrict__ x) {
  if constexpr (COL < 36)
    return x[COL % 9];
  else
    return x[9 + (COL - 36) % 13];
}

// fold one lo=4 component K4: 4 path t-values -> 4 copies -> staging
template <int K4>
__device__ __forceinline__ void fold4(float* __restrict__ pool, int tid,
                                      const float* __restrict__ x,
                                      const float* __restrict__ y,
                                      const float* __restrict__ w4) {
  const float t0 = tp_k<4, 4, 4, K4>(x, y);
  const float t1 = tp_k<4, 6, 4, K4>(x, y + 9);
  const float t2 = tp_k<6, 4, 4, K4>(x + 9, y);
  const float t3 = tp_k<6, 6, 4, K4>(x + 9, y + 9);
#pragma unroll
  for (int c = 0; c < 4; ++c) {
    float v = w4[c * 4 + 0] * t0 + w4[c * 4 + 1] * t1 + w4[c * 4 + 2] * t2 +
              w4[c * 4 + 3] * t3;
    if (c == 0) v += res_of<K4 + 0 * 22>(x);
    if (c == 1) v += res_of<K4 + 1 * 22>(x);
    if (c == 2) v += res_of<K4 + 2 * 22>(x);
    if (c == 3) v += res_of<K4 + 3 * 22>(x);
    pool[(c * 22 + K4) * SSTR + tid] = v;
  }
}

// fold one lo=6 component K6
template <int K6>
__device__ __forceinline__ void fold6(float* __restrict__ pool, int tid,
                                      const float* __restrict__ x,
                                      const float* __restrict__ y,
                                      const float* __restrict__ w6) {
  const float s0 = tp_k<4, 4, 6, K6>(x, y);
  const float s1 = tp_k<4, 6, 6, K6>(x, y + 9);
  const float s2 = tp_k<6, 4, 6, K6>(x + 9, y);
  const float s3 = tp_k<6, 6, 6, K6>(x + 9, y + 9);
#pragma unroll
  for (int c = 0; c < 4; ++c) {
    float v = w6[c * 4 + 0] * s0 + w6[c * 4 + 1] * s1 + w6[c * 4 + 2] * s2 +
              w6[c * 4 + 3] * s3;
    if (c == 0) v += res_of<9 + K6 + 0 * 22>(x);
    if (c == 1) v += res_of<9 + K6 + 1 * 22>(x);
    if (c == 2) v += res_of<9 + K6 + 2 * 22>(x);
    if (c == 3) v += res_of<9 + K6 + 3 * 22>(x);
    pool[(c * 22 + 9 + K6) * SSTR + tid] = v;
  }
}

// one magnetic quantum number m = M: +m and -m components of both lo=4 and
// lo=6 share the same x_i*y_j product set -> emit them in ONE inline scope so
// ptxas CSEs the products.
template <int M>
__device__ __forceinline__ void emit_m(float* pool, int tid, const float* x,
                                       const float* y, const float* w4,
                                       const float* w6) {
  if constexpr (M <= 4) {
    fold4<4 + M>(pool, tid, x, y, w4);
    if constexpr (M > 0) fold4<4 - M>(pool, tid, x, y, w4);
  }
  fold6<6 + M>(pool, tid, x, y, w6);
  if constexpr (M > 0) fold6<6 - M>(pool, tid, x, y, w6);
}

template <int... Ms>
__device__ __forceinline__ void emit_all(float* pool, int tid, const float* x,
                                         const float* y, const float* w4,
                                         const float* w6,
                                         std::integer_sequence<int, Ms...>) {
  (emit_m<Ms>(pool, tid, x, y, w4, w6), ...);
}

// ============================================================================
// Main kernel
// ============================================================================
__global__ __launch_bounds__(TILE, 4) void esc_kernel(
    const float* __restrict__ f4, const float* __restrict__ f6,
    const float* __restrict__ sw, const float* __restrict__ tw,
    float* __restrict__ out, int H, int W) {
  __shared__ float pool[POOLN];

  const int tid = threadIdx.x;
  const int h = blockIdx.y;
  const int w0 = blockIdx.x * TILE;
  const bool valid = (w0 + tid) < W;

  // ---- phase A: halo copy, global-packed layout, division-free
  for (int px = tid; px < NPX; px += TILE) {
    int gw = w0 - 1 + px;
    gw = gw < 0 ? 0 : (gw >= W ? W - 1 : gw);
#pragma unroll
    for (int r = 0; r < 3; ++r) {
      int gh = h - 1 + r;
      gh = gh < 0 ? 0 : (gh >= H ? H - 1 : gh);
      const long nn = (long)gh * W + gw;
      const float* s4 = f4 + nn * 9;
      float* d4 = pool + r * (NPX * 9) + px * 9;
#pragma unroll
      for (int c = 0; c < 9; ++c) d4[c] = __ldg(s4 + c);
      const float* s6 = f6 + nn * 13;
      float* d6 = pool + F6OFF + r * (NPX * 13) + px * 13;
#pragma unroll
      for (int c = 0; c < 13; ++c) d6[c] = __ldg(s6 + c);
    }
  }
  __syncthreads();

  // ---- phase B1: depthwise 3x3 conv -> x[22], y[22]
  float x[22], y[22];
  if (valid) {
    float s9[9];
#pragma unroll
    for (int i = 0; i < 9; ++i) s9[i] = __ldg(sw + i);
#pragma unroll
    for (int ch = 0; ch < 9; ++ch) {
      float a = 0.f;
#pragma unroll
      for (int dr = 0; dr < 3; ++dr)
#pragma unroll
        for (int dc = 0; dc < 3; ++dc)
          a += s9[dr * 3 + dc] * pool[dr * (NPX * 9) + (tid + dc) * 9 + ch];
      y[ch] = a;
      x[ch] = pool[1 * (NPX * 9) + (tid + 1) * 9 + ch];
    }
#pragma unroll
    for (int ch = 0; ch < 13; ++ch) {
      float a = 0.f;
#pragma unroll
      for (int dr = 0; dr < 3; ++dr)
#pragma unroll
        for (int dc = 0; dc < 3; ++dc)
          a += s9[dr * 3 + dc] *
               pool[F6OFF + dr * (NPX * 13) + (tid + dc) * 13 + ch];
      y[9 + ch] = a;
      x[9 + ch] = pool[F6OFF + 1 * (NPX * 13) + (tid + 1) * 13 + ch];
    }
  }
  __syncthreads();  // conv tiles dead; pool becomes staging

  // ---- phase B2: streamed tensor products, grouped by |m|
  if (valid) {
    const float A4 = 1.5f;                 // sqrt(9/4)
    const float A6 = 1.8027756377319946f;  // sqrt(13/4)
    float w4[16], w6[16];
#pragma unroll
    for (int c = 0; c < 4; ++c)
#pragma unroll
      for (int p = 0; p < 4; ++p) {
        w4[c * 4 + p] = A4 * __ldg(tw + c * 8 + p);
        w6[c * 4 + p] = A6 * __ldg(tw + c * 8 + 4 + p);
      }

    emit_all(pool, tid, x, y, w4, w6, std::make_integer_sequence<int, 7>{});
  }
  __syncthreads();

  // ---- phase C: cooperative coalesced float4 stores
  const long rowbase = (long)h * W;
#pragma unroll
  for (int it = 0; it < 9; ++it) {
    int e = it * TILE + tid;
    int px = e / 9;
    int g = e - px * 9;
    int wp = w0 + px;
    if (wp < W) {
      int s = g * 4;
      float4 v =
          make_float4(pool[(s + 0) * SSTR + px], pool[(s + 1) * SSTR + px],
                      pool[(s + 2) * SSTR + px], pool[(s + 3) * SSTR + px]);
      *reinterpret_cast<float4*>(out + (rowbase + wp) * 36 + s) = v;
    }
  }
  float* out2 = out + (long)H * W * 36;
#pragma unroll
  for (int it = 0; it < 13; ++it) {
    int e = it * TILE + tid;
    int px = e / 13;
    int g = e - px * 13;
    int wp = w0 + px;
    if (wp < W) {
      int s = 36 + g * 4;
      float4 v =
          make_float4(pool[(s + 0) * SSTR + px], pool[(s + 1) * SSTR + px],
                      pool[(s + 2) * SSTR + px], pool[(s + 3) * SSTR + px]);
      *reinterpret_cast<float4*>(out2 + (rowbase + wp) * 52 + g * 4) = v;
    }
  }
}

// ============================================================================
extern "C" void kernel_launch(void* const* d_in, const int* in_sizes, int n_in,
                              void* d_out, int out_size) {
  (void)n_in;
  (void)out_size;
  const float* f4 = (const float*)d_in[0];
  const float* f6 = (const float*)d_in[1];
  const float* sw = (const float*)d_in[2];
  const float* tw = (const float*)d_in[3];
  float* out = (float*)d_out;

  const long n = (long)in_sizes[0] / 9;  // HW
  int W = (int)(sqrt((double)n) + 0.5);  // H = W = 768 here
  if (W < 1) W = 1;
  int H = (int)(n / W);

  dim3 grid((W + TILE - 1) / TILE, H);
  esc_kernel<<<grid, TILE>>>(f4, f6, sw, tw, out, H, W);
}